// round 2
// baseline (speedup 1.0000x reference)
#include <cuda_runtime.h>
#include <math.h>

#define BATCHN 2
#define SEQ    2048
#define BLTOT  4096
#define DM     1024
#define DIN    2048
#define NH     32
#define HD     64
#define NK     32
#define CONVD  2176
#define DPROJ  4256
#define NCH    32
#define CH     64
#define LR     48
#define XBC_OFF 2048
#define DT_OFF  4224
#define THETA_CLIPF 1.5707963267948966f

// ---------------- scratch (static device globals; no allocation) ----------------
__device__ __align__(256) float g_zx [BLTOT*DPROJ];
__device__ __align__(256) float g_dt [BLTOT*NH];
__device__ __align__(256) float g_xs [BLTOT*DIN];
__device__ __align__(256) float g_Br [BLTOT*NK];
__device__ __align__(256) float g_Bi [BLTOT*NK];
__device__ __align__(256) float g_Cr [BLTOT*NK];
__device__ __align__(256) float g_Ci [BLTOT*NK];
__device__ __align__(256) float g_t1 [BLTOT*LR];
__device__ __align__(256) float g_lzr[BLTOT*NH*NK];
__device__ __align__(256) float g_lzi[BLTOT*NH*NK];
__device__ __align__(256) float g_Pr [BATCHN*NCH*NH*CH*NK];
__device__ __align__(256) float g_Pi [BATCHN*NCH*NH*CH*NK];
__device__ __align__(256) float g_Er [BATCHN*NCH*NH*NK];
__device__ __align__(256) float g_Ei [BATCHN*NCH*NH*NK];
__device__ __align__(256) float g_Dr [BATCHN*NCH*NH*HD*NK];
__device__ __align__(256) float g_Di [BATCHN*NCH*NH*HD*NK];
__device__ __align__(256) float g_Sr [BATCHN*NCH*NH*HD*NK];
__device__ __align__(256) float g_Si [BATCHN*NCH*NH*HD*NK];
__device__ __align__(256) float g_y  [BLTOT*DIN];
__device__ __align__(256) float g_gv [BLTOT*DIN];

// ---------------- GEMM: C[M,N] = A[M,K] * W[N,K]^T (both row-major, K-contig) ---
__global__ __launch_bounds__(256) void gemm_nt(const float* __restrict__ A,
                                               const float* __restrict__ W,
                                               float* __restrict__ C,
                                               int M, int N, int Kd)
{
    __shared__ float As[8][132];
    __shared__ float Ws[8][132];
    int tid = threadIdx.x;
    int tr = tid >> 4, tc = tid & 15;
    int row0 = blockIdx.y * 128, col0 = blockIdx.x * 128;
    int lr = tid >> 1;
    int lk = (tid & 1) * 4;

    float acc[8][8];
    #pragma unroll
    for (int i = 0; i < 8; i++) {
        #pragma unroll
        for (int j = 0; j < 8; j++) acc[i][j] = 0.f;
    }

    const float* Ap = A + (size_t)(row0 + lr) * Kd + lk;
    bool wvalid = (col0 + lr) < N;
    const float* Wp = W + (size_t)(col0 + lr) * Kd + lk;

    for (int k0 = 0; k0 < Kd; k0 += 8) {
        float4 av = *(const float4*)(Ap + k0);
        float4 wv = wvalid ? *(const float4*)(Wp + k0) : make_float4(0.f,0.f,0.f,0.f);
        As[lk+0][lr] = av.x; As[lk+1][lr] = av.y; As[lk+2][lr] = av.z; As[lk+3][lr] = av.w;
        Ws[lk+0][lr] = wv.x; Ws[lk+1][lr] = wv.y; Ws[lk+2][lr] = wv.z; Ws[lk+3][lr] = wv.w;
        __syncthreads();
        #pragma unroll
        for (int kk = 0; kk < 8; kk++) {
            float a[8], b[8];
            #pragma unroll
            for (int i = 0; i < 8; i++) a[i] = As[kk][tr*8 + i];
            #pragma unroll
            for (int j = 0; j < 8; j++) b[j] = Ws[kk][tc*8 + j];
            #pragma unroll
            for (int i = 0; i < 8; i++) {
                #pragma unroll
                for (int j = 0; j < 8; j++) acc[i][j] += a[i] * b[j];
            }
        }
        __syncthreads();
    }

    #pragma unroll
    for (int i = 0; i < 8; i++) {
        int r = row0 + tr*8 + i;
        #pragma unroll
        for (int j = 0; j < 8; j++) {
            int cc = col0 + tc*8 + j;
            if (cc < N) C[(size_t)r * N + cc] = acc[i][j];
        }
    }
}

// ---------------- dt = softplus(zx[:, DT_OFF+h] + dt_bias[h]) --------------------
__global__ void dt_kernel(const float* __restrict__ dt_bias)
{
    int idx = blockIdx.x * blockDim.x + threadIdx.x;
    if (idx >= BLTOT * NH) return;
    int bl = idx >> 5, hh = idx & 31;
    float v = g_zx[(size_t)bl * DPROJ + DT_OFF + hh] + dt_bias[hh];
    float sp = (v > 20.f) ? v : log1pf(expf(v));
    g_dt[idx] = sp;
}

// ---------------- depthwise causal conv (width 4) + silu + split -----------------
__global__ void conv_kernel(const float* __restrict__ conv_w,
                            const float* __restrict__ conv_b)
{
    int c = blockIdx.x * blockDim.x + threadIdx.x;
    if (c >= CONVD) return;
    int bl = blockIdx.y;
    int l = bl & (SEQ - 1);
    float acc = conv_b[c];
    #pragma unroll
    for (int kk = 0; kk < 4; kk++) {
        int lt = l + kk - 3;
        if (lt >= 0)
            acc += g_zx[(size_t)(bl + kk - 3) * DPROJ + XBC_OFF + c] * conv_w[c*4 + kk];
    }
    float a = acc / (1.f + __expf(-acc));
    if (c < DIN) {
        g_xs[(size_t)bl * DIN + c] = a;
    } else {
        int c2 = c - DIN;
        if (c2 < 64) {
            int k = c2 >> 1;
            if (c2 & 1) g_Bi[bl*NK + k] = a; else g_Br[bl*NK + k] = a;
        } else {
            int c3 = c2 - 64;
            int k = c3 >> 1;
            if (c3 & 1) g_Ci[bl*NK + k] = a; else g_Cr[bl*NK + k] = a;
        }
    }
}

// ---------------- t1 = tanh(x @ theta_w1)  [BL,48] -------------------------------
__global__ __launch_bounds__(192) void lora1_kernel(const float* __restrict__ x,
                                                    const float* __restrict__ w1)
{
    __shared__ float xs[DM];
    __shared__ float part[4][LR];
    int bl = blockIdx.x, tid = threadIdx.x;
    for (int j = tid; j < DM; j += 192) xs[j] = x[(size_t)bl * DM + j];
    __syncthreads();
    int n = tid % LR, kg = tid / LR;   // kg in 0..3
    float acc = 0.f;
    for (int kk = kg; kk < DM; kk += 4) acc += xs[kk] * w1[kk*LR + n];
    part[kg][n] = acc;
    __syncthreads();
    if (tid < LR) {
        float s = part[0][tid] + part[1][tid] + part[2][tid] + part[3][tid];
        g_t1[bl*LR + tid] = tanhf(s);
    }
}

// ---------------- lora2 -> theta -> lambda_eff -> log_z --------------------------
__global__ __launch_bounds__(256) void lora2_kernel(const float* __restrict__ w2,
                                                    const float* __restrict__ theta_base,
                                                    const float* __restrict__ lambda_base,
                                                    const float* __restrict__ eta)
{
    __shared__ float t1s[LR];
    int bl = blockIdx.x, tid = threadIdx.x;
    if (tid < LR) t1s[tid] = g_t1[bl*LR + tid];
    __syncthreads();
    for (int n = tid; n < NH*NK; n += 256) {
        float acc = 0.f;
        #pragma unroll
        for (int j = 0; j < LR; j++) acc += t1s[j] * w2[j*(NH*NK) + n];
        float th = theta_base[n] + acc;
        th = fminf(fmaxf(th, -THETA_CLIPF), THETA_CLIPF);
        float lam = lambda_base[n] + eta[n] * th * th;
        float dtv = g_dt[bl*NH + (n >> 5)];
        g_lzr[(size_t)bl*(NH*NK) + n] = -lam * dtv;
        g_lzi[(size_t)bl*(NH*NK) + n] =  th * dtv;
    }
}

// ---------------- per-chunk kernel: cumlog, G, y_intra, P/E, D -------------------
// block = (b, chunk, head)
// NOTE (reference semantics): scaled_B = A * bc[:, :, None] puts B at index t,
// not s. So G[t,s] = Re( sum_k C[t,k]*B[t,k]*exp(cl[t]-cl[s]) ), and the chunk
// state increment is D_c[p,k] = B[63,k] * sum_s exp(cl[63]-cl[s]) * xd[s,p].
__global__ __launch_bounds__(256) void chunk_kernel(const float* __restrict__ Dvec)
{
    extern __shared__ float sm[];
    float* clr = sm;                 // 64 x 33
    float* cli = sm + 2112;
    float* Bre = sm + 2*2112;
    float* Bim = sm + 3*2112;
    float* Cre = sm + 4*2112;       // later holds cb = C*B, then w = exp(cl63-cl[s])
    float* Cim = sm + 5*2112;
    float* xd  = sm + 6*2112;        // 64 x 65
    float* G   = sm + 6*2112 + 4160; // 64 x 65

    int tid = threadIdx.x;
    int bid = blockIdx.x;
    int h = bid & 31;
    int c = (bid >> 5) & 31;
    int b = bid >> 10;
    int blbase = b * SEQ + c * CH;

    for (int e = tid; e < CH*NK; e += 256) {
        int t = e >> 5, k = e & 31;
        int bl = blbase + t;
        clr[t*33+k] = g_lzr[(size_t)bl*(NH*NK) + h*NK + k];
        cli[t*33+k] = g_lzi[(size_t)bl*(NH*NK) + h*NK + k];
        Bre[t*33+k] = g_Br[bl*NK + k];
        Bim[t*33+k] = g_Bi[bl*NK + k];
        Cre[t*33+k] = g_Cr[bl*NK + k];
        Cim[t*33+k] = g_Ci[bl*NK + k];
    }
    for (int e = tid; e < CH*HD; e += 256) {
        int t = e >> 6, p = e & 63;
        int bl = blbase + t;
        xd[t*65+p] = g_xs[(size_t)bl*DIN + h*HD + p] * g_dt[bl*NH + h];
    }
    __syncthreads();

    // cumulative sum of log_z over t (per k, warp 0)
    if (tid < 32) {
        float sr = 0.f, si = 0.f;
        for (int t = 0; t < CH; t++) {
            sr += clr[t*33+tid]; si += cli[t*33+tid];
            clr[t*33+tid] = sr;  cli[t*33+tid] = si;
        }
    }
    __syncthreads();

    // P[t,k] = C[t,k]*exp(cumlog[t,k]) ; E[k] = exp(cumlog[63,k])
    for (int e = tid; e < CH*NK; e += 256) {
        int t = e >> 5, k = e & 31;
        float er = __expf(clr[t*33+k]);
        float sn, cs; __sincosf(cli[t*33+k], &sn, &cs);
        float exr = er*cs, exi = er*sn;
        float cr = Cre[t*33+k], ci = Cim[t*33+k];
        size_t base = (size_t)bid*(CH*NK) + t*NK + k;
        g_Pr[base] = cr*exr - ci*exi;
        g_Pi[base] = cr*exi + ci*exr;
        if (t == CH-1) { g_Er[bid*NK + k] = exr; g_Ei[bid*NK + k] = exi; }
    }
    __syncthreads();

    // cb[t,k] = C[t,k]*B[t,k]  (overwrite Cre/Cim)
    for (int e = tid; e < CH*NK; e += 256) {
        int t = e >> 5, k = e & 31;
        float cr = Cre[t*33+k], ci = Cim[t*33+k];
        float br = Bre[t*33+k], bi = Bim[t*33+k];
        Cre[t*33+k] = cr*br - ci*bi;
        Cim[t*33+k] = cr*bi + ci*br;
    }
    __syncthreads();

    // G[t,s] = Re( sum_k cb[t,k]*exp(cl[t]-cl[s]) ), s<=t
    for (int e = tid; e < CH*CH; e += 256) {
        int t = e >> 6, s = e & 63;
        float acc = 0.f;
        if (s <= t) {
            #pragma unroll 4
            for (int k = 0; k < NK; k++) {
                float dr = clr[t*33+k] - clr[s*33+k];
                float di = cli[t*33+k] - cli[s*33+k];
                float er = __expf(dr);
                float sn, cs; __sincosf(di, &sn, &cs);
                acc += er * (Cre[t*33+k]*cs - Cim[t*33+k]*sn);
            }
        }
        G[t*65+s] = acc;
    }
    __syncthreads();

    // y_intra + D skip term
    float Dh = Dvec[h];
    for (int e = tid; e < CH*HD; e += 256) {
        int t = e >> 6, p = e & 63;
        float acc = 0.f;
        for (int s = 0; s <= t; s++) acc += G[t*65+s] * xd[s*65+p];
        size_t yi = (size_t)(blbase + t)*DIN + h*HD + p;
        g_y[yi] = acc + Dh * g_xs[yi];
    }

    // w[s,k] = exp(cl[63]-cl[s])  (overwrite Cre/Cim; cb no longer needed)
    for (int e = tid; e < CH*NK; e += 256) {
        int s = e >> 5, k = e & 31;
        float dr = clr[(CH-1)*33+k] - clr[s*33+k];
        float di = cli[(CH-1)*33+k] - cli[s*33+k];
        float er = __expf(dr);
        float sn, cs; __sincosf(di, &sn, &cs);
        Cre[s*33+k] = er*cs;
        Cim[s*33+k] = er*sn;
    }
    __syncthreads();

    // D_c[p,k] = B[63,k] * sum_s w[s,k] * xd[s,p]   (complex)
    for (int e = tid; e < HD*NK; e += 256) {
        int p = e >> 5, k = e & 31;
        float ar = 0.f, ai = 0.f;
        #pragma unroll 8
        for (int s = 0; s < CH; s++) {
            float xv = xd[s*65+p];
            ar += xv * Cre[s*33+k];
            ai += xv * Cim[s*33+k];
        }
        float br = Bre[(CH-1)*33+k], bi = Bim[(CH-1)*33+k];
        size_t di_ = (size_t)bid*(HD*NK) + p*NK + k;
        g_Dr[di_] = br*ar - bi*ai;
        g_Di[di_] = br*ai + bi*ar;
    }
}

// ---------------- sequential scan over chunks (per b,h,p,k) ----------------------
__global__ void scan_kernel()
{
    int idx = blockIdx.x * blockDim.x + threadIdx.x;
    int k = idx & 31;
    int p = (idx >> 5) & 63;
    int h = (idx >> 11) & 31;
    int b = idx >> 16;
    float sr = 0.f, si = 0.f;
    for (int c = 0; c < NCH; c++) {
        int bidl = (b*NCH + c)*NH + h;
        size_t di_ = (size_t)bidl*(HD*NK) + p*NK + k;
        g_Sr[di_] = sr; g_Si[di_] = si;
        float er = g_Er[bidl*NK + k], ei = g_Ei[bidl*NK + k];
        float dr = g_Dr[di_], dimg = g_Di[di_];
        float nr = er*sr - ei*si + dr;
        float ni = er*si + ei*sr + dimg;
        sr = nr; si = ni;
    }
}

// ---------------- y += Re( P[t,k] * S_entry[p,k] ) -------------------------------
__global__ __launch_bounds__(256) void yinter_kernel()
{
    __shared__ float Pr[2112], Pi[2112], Sr[2112], Si[2112];
    int tid = threadIdx.x, bid = blockIdx.x;
    int h = bid & 31, c = (bid >> 5) & 31, b = bid >> 10;
    size_t base = (size_t)bid * (CH*NK);
    for (int e = tid; e < CH*NK; e += 256) {
        int t = e >> 5, k = e & 31;
        Pr[t*33+k] = g_Pr[base + e];
        Pi[t*33+k] = g_Pi[base + e];
        Sr[t*33+k] = g_Sr[base + e];   // rows here are p
        Si[t*33+k] = g_Si[base + e];
    }
    __syncthreads();
    int blbase = b*SEQ + c*CH;
    for (int e = tid; e < CH*HD; e += 256) {
        int t = e >> 6, p = e & 63;
        float acc = 0.f;
        #pragma unroll 8
        for (int k = 0; k < NK; k++)
            acc += Pr[t*33+k]*Sr[p*33+k] - Pi[t*33+k]*Si[p*33+k];
        size_t yi = (size_t)(blbase + t)*DIN + h*HD + p;
        g_y[yi] += acc;
    }
}

// ---------------- gating + RMSNorm ----------------------------------------------
__global__ __launch_bounds__(256) void gatenorm_kernel(const float* __restrict__ norm_w)
{
    __shared__ float red[8];
    int bl = blockIdx.x, tid = threadIdx.x;
    float local = 0.f;
    for (int j = tid; j < DIN; j += 256) {
        float z = g_zx[(size_t)bl*DPROJ + j];
        float y = g_y[(size_t)bl*DIN + j];
        float sig = 1.f / (1.f + __expf(-z));
        float g = y * z * sig;
        g_gv[(size_t)bl*DIN + j] = g;
        local += g * g;
    }
    #pragma unroll
    for (int o = 16; o; o >>= 1) local += __shfl_xor_sync(0xffffffffu, local, o);
    if ((tid & 31) == 0) red[tid >> 5] = local;
    __syncthreads();
    if (tid == 0) {
        float s = 0.f;
        for (int i = 0; i < 8; i++) s += red[i];
        red[0] = rsqrtf(s / (float)DIN + 1e-5f);
    }
    __syncthreads();
    float sc = red[0];
    for (int j = tid; j < DIN; j += 256)
        g_gv[(size_t)bl*DIN + j] *= sc * norm_w[j];
}

// ---------------- launch ---------------------------------------------------------
extern "C" void kernel_launch(void* const* d_in, const int* in_sizes, int n_in,
                              void* d_out, int out_size)
{
    (void)in_sizes; (void)n_in; (void)out_size;
    const float* x       = (const float*)d_in[0];
    const float* in_w    = (const float*)d_in[1];
    const float* conv_w  = (const float*)d_in[2];
    const float* conv_b  = (const float*)d_in[3];
    const float* dt_bias = (const float*)d_in[4];
    const float* lam_b   = (const float*)d_in[5];
    const float* th_b    = (const float*)d_in[6];
    const float* w1      = (const float*)d_in[7];
    const float* w2      = (const float*)d_in[8];
    const float* eta     = (const float*)d_in[9];
    const float* Dv      = (const float*)d_in[10];
    const float* nw      = (const float*)d_in[11];
    const float* out_w   = (const float*)d_in[12];
    float* out = (float*)d_out;

    float *zx = nullptr, *gg = nullptr;
    cudaGetSymbolAddress((void**)&zx, g_zx);
    cudaGetSymbolAddress((void**)&gg, g_gv);

    // 1) in_proj GEMM: [4096,1024] x [4256,1024]^T
    gemm_nt<<<dim3((DPROJ + 127)/128, BLTOT/128), 256>>>(x, in_w, zx, BLTOT, DPROJ, DM);
    // 2) dt
    dt_kernel<<<(BLTOT*NH + 255)/256, 256>>>(dt_bias);
    // 3) conv + silu + split
    conv_kernel<<<dim3((CONVD + 255)/256, BLTOT), 256>>>(conv_w, conv_b);
    // 4) lora stage 1
    lora1_kernel<<<BLTOT, 192>>>(x, w1);
    // 5) lora stage 2 + log_z
    lora2_kernel<<<BLTOT, 256>>>(w2, th_b, lam_b, eta);
    // 6) chunk-parallel heavy kernel
    cudaFuncSetAttribute(chunk_kernel, cudaFuncAttributeMaxDynamicSharedMemorySize, 84*1024);
    chunk_kernel<<<BATCHN*NCH*NH, 256, 83968>>>(Dv);
    // 7) inter-chunk state scan
    scan_kernel<<<(BATCHN*NH*HD*NK)/256, 256>>>();
    // 8) y += P * S_entry
    yinter_kernel<<<BATCHN*NCH*NH, 256>>>();
    // 9) gate + rmsnorm
    gatenorm_kernel<<<BLTOT, 256>>>(nw);
    // 10) out_proj GEMM: [4096,2048] x [1024,2048]^T
    gemm_nt<<<dim3(DM/128, BLTOT/128), 256>>>(gg, out_w, out, BLTOT, DM, DIN);
}

// round 3
// speedup vs baseline: 1.6049x; 1.6049x over previous
#include <cuda_runtime.h>
#include <cuda_bf16.h>
#include <math.h>

#define BATCHN 2
#define SEQ    2048
#define BLTOT  4096
#define DM     1024
#define DIN    2048
#define NH     32
#define HD     64
#define NK     32
#define CONVD  2176
#define DPROJ  4256
#define NCH    32
#define CH     64
#define LR     48
#define XBC_OFF 2048
#define DT_OFF  4224
#define THETA_CLIPF 1.5707963267948966f

// ---------------- scratch (static device globals; no allocation) ----------------
__device__ __align__(256) float g_zx [BLTOT*DPROJ];
__device__ __align__(256) float g_dt [BLTOT*NH];
__device__ __align__(256) float g_xs [BLTOT*DIN];
__device__ __align__(256) float g_Br [BLTOT*NK];
__device__ __align__(256) float g_Bi [BLTOT*NK];
__device__ __align__(256) float g_Cr [BLTOT*NK];
__device__ __align__(256) float g_Ci [BLTOT*NK];
__device__ __align__(256) float g_t1 [BLTOT*LR];
__device__ __align__(256) float g_lzr[BLTOT*NH*NK];
__device__ __align__(256) float g_lzi[BLTOT*NH*NK];
__device__ __align__(256) float g_Pr [BATCHN*NCH*NH*CH*NK];
__device__ __align__(256) float g_Pi [BATCHN*NCH*NH*CH*NK];
__device__ __align__(256) float g_Er [BATCHN*NCH*NH*NK];
__device__ __align__(256) float g_Ei [BATCHN*NCH*NH*NK];
__device__ __align__(256) float g_Dr [BATCHN*NCH*NH*HD*NK];
__device__ __align__(256) float g_Di [BATCHN*NCH*NH*HD*NK];
__device__ __align__(256) float g_Sr [BATCHN*NCH*NH*HD*NK];
__device__ __align__(256) float g_Si [BATCHN*NCH*NH*HD*NK];
__device__ __align__(256) float g_y  [BLTOT*DIN];
__device__ __align__(256) float g_gv [BLTOT*DIN];

// ================= tensor-core GEMM (bf16 2-term split, mma.sync) ===============
// C[M,N] = A[M,K] * W[N,K]^T  (both K-contiguous).  fp32 in/out, internally
// hiA*hiB + hiA*loB + loA*hiB with bf16 fragments, fp32 accumulate.
#define LDSM4(R0,R1,R2,R3,ADDR) \
    asm volatile("ldmatrix.sync.aligned.m8n8.x4.shared.b16 {%0,%1,%2,%3}, [%4];" \
                 : "=r"(R0),"=r"(R1),"=r"(R2),"=r"(R3) : "r"(ADDR))

__device__ __forceinline__ void mma_bf16(float* d, const unsigned* a,
                                         unsigned b0, unsigned b1)
{
    asm volatile("mma.sync.aligned.m16n8k16.row.col.f32.bf16.bf16.f32 "
                 "{%0,%1,%2,%3}, {%4,%5,%6,%7}, {%8,%9}, {%0,%1,%2,%3};"
                 : "+f"(d[0]), "+f"(d[1]), "+f"(d[2]), "+f"(d[3])
                 : "r"(a[0]), "r"(a[1]), "r"(a[2]), "r"(a[3]), "r"(b0), "r"(b1));
}

__device__ __forceinline__ unsigned smem_u32(const void* p)
{
    return (unsigned)__cvta_generic_to_shared(p);
}

__device__ __forceinline__ void split_store(float4 v,
                                            __nv_bfloat16* hi, __nv_bfloat16* lo)
{
    float xs[4] = {v.x, v.y, v.z, v.w};
    __nv_bfloat16 h[4], l[4];
    #pragma unroll
    for (int i = 0; i < 4; i++) {
        h[i] = __float2bfloat16(xs[i]);
        l[i] = __float2bfloat16(xs[i] - __bfloat162float(h[i]));
    }
    __nv_bfloat162 t;
    t.x = h[0]; t.y = h[1]; ((__nv_bfloat162*)hi)[0] = t;
    t.x = h[2]; t.y = h[3]; ((__nv_bfloat162*)hi)[1] = t;
    t.x = l[0]; t.y = l[1]; ((__nv_bfloat162*)lo)[0] = t;
    t.x = l[2]; t.y = l[3]; ((__nv_bfloat162*)lo)[1] = t;
}

#define SMSTR 40   // padded smem row stride (in bf16) -> conflict-free ldmatrix

__global__ __launch_bounds__(256) void gemm_tc(const float* __restrict__ A,
                                               const float* __restrict__ W,
                                               float* __restrict__ C,
                                               int M, int N, int Kd)
{
    extern __shared__ __align__(16) unsigned char smraw[];
    __nv_bfloat16* aHi = (__nv_bfloat16*)smraw;          // [128][SMSTR]
    __nv_bfloat16* aLo = aHi + 128*SMSTR;
    __nv_bfloat16* bHi = aLo + 128*SMSTR;
    __nv_bfloat16* bLo = bHi + 128*SMSTR;

    int tid = threadIdx.x, lane = tid & 31, wid = tid >> 5;
    int wm = wid & 3;          // m offset = 32*wm
    int wn = wid >> 2;         // n offset = 64*wn
    int row0 = blockIdx.y * 128, col0 = blockIdx.x * 128;

    float acc[2][8][4];
    #pragma unroll
    for (int a = 0; a < 2; a++)
        #pragma unroll
        for (int b = 0; b < 8; b++)
            #pragma unroll
            for (int c = 0; c < 4; c++) acc[a][b][c] = 0.f;

    float4 pa[4], pb[4];
    int NT = Kd >> 5;

    // prologue: load tile 0
    #pragma unroll
    for (int i = 0; i < 4; i++) {
        int f = tid + i*256, r = f >> 3, kq = f & 7;
        pa[i] = *(const float4*)(A + (size_t)(row0 + r)*Kd + kq*4);
        int wr = col0 + r;
        pb[i] = (wr < N) ? *(const float4*)(W + (size_t)wr*Kd + kq*4)
                         : make_float4(0.f,0.f,0.f,0.f);
    }
    #pragma unroll
    for (int i = 0; i < 4; i++) {
        int f = tid + i*256, r = f >> 3, kq = f & 7;
        split_store(pa[i], &aHi[r*SMSTR + kq*4], &aLo[r*SMSTR + kq*4]);
        split_store(pb[i], &bHi[r*SMSTR + kq*4], &bLo[r*SMSTR + kq*4]);
    }
    __syncthreads();

    for (int kt = 0; kt < NT; kt++) {
        if (kt + 1 < NT) {
            int k0 = (kt + 1) << 5;
            #pragma unroll
            for (int i = 0; i < 4; i++) {
                int f = tid + i*256, r = f >> 3, kq = f & 7;
                pa[i] = *(const float4*)(A + (size_t)(row0 + r)*Kd + k0 + kq*4);
                int wr = col0 + r;
                pb[i] = (wr < N) ? *(const float4*)(W + (size_t)wr*Kd + k0 + kq*4)
                                 : make_float4(0.f,0.f,0.f,0.f);
            }
        }

        #pragma unroll
        for (int kh = 0; kh < 32; kh += 16) {
            unsigned ah[2][4], al[2][4];
            #pragma unroll
            for (int mf = 0; mf < 2; mf++) {
                int r = wm*32 + mf*16 + (lane & 15);
                int cc = kh + ((lane >> 4) << 3);
                unsigned adr = smem_u32(&aHi[r*SMSTR + cc]);
                LDSM4(ah[mf][0], ah[mf][1], ah[mf][2], ah[mf][3], adr);
                adr = smem_u32(&aLo[r*SMSTR + cc]);
                LDSM4(al[mf][0], al[mf][1], al[mf][2], al[mf][3], adr);
            }
            #pragma unroll
            for (int np = 0; np < 4; np++) {
                int nr  = wn*64 + np*16 + (lane & 7) + ((lane >> 4) << 3);
                int kof = kh + (((lane >> 3) & 1) << 3);
                unsigned bh[4], bl[4];
                unsigned adr = smem_u32(&bHi[nr*SMSTR + kof]);
                LDSM4(bh[0], bh[1], bh[2], bh[3], adr);
                adr = smem_u32(&bLo[nr*SMSTR + kof]);
                LDSM4(bl[0], bl[1], bl[2], bl[3], adr);
                #pragma unroll
                for (int mf = 0; mf < 2; mf++) {
                    mma_bf16(acc[mf][np*2+0], ah[mf], bh[0], bh[1]);
                    mma_bf16(acc[mf][np*2+0], ah[mf], bl[0], bl[1]);
                    mma_bf16(acc[mf][np*2+0], al[mf], bh[0], bh[1]);
                    mma_bf16(acc[mf][np*2+1], ah[mf], bh[2], bh[3]);
                    mma_bf16(acc[mf][np*2+1], ah[mf], bl[2], bl[3]);
                    mma_bf16(acc[mf][np*2+1], al[mf], bh[2], bh[3]);
                }
            }
        }
        __syncthreads();
        if (kt + 1 < NT) {
            #pragma unroll
            for (int i = 0; i < 4; i++) {
                int f = tid + i*256, r = f >> 3, kq = f & 7;
                split_store(pa[i], &aHi[r*SMSTR + kq*4], &aLo[r*SMSTR + kq*4]);
                split_store(pb[i], &bHi[r*SMSTR + kq*4], &bLo[r*SMSTR + kq*4]);
            }
            __syncthreads();
        }
    }

    // epilogue
    #pragma unroll
    for (int mf = 0; mf < 2; mf++) {
        int r = row0 + wm*32 + mf*16 + (lane >> 2);
        #pragma unroll
        for (int nf = 0; nf < 8; nf++) {
            int c = col0 + wn*64 + nf*8 + ((lane & 3) << 1);
            if (c < N) {
                C[(size_t)r*N + c]       = acc[mf][nf][0];
                C[(size_t)(r+8)*N + c]   = acc[mf][nf][2];
            }
            if (c + 1 < N) {
                C[(size_t)r*N + c + 1]     = acc[mf][nf][1];
                C[(size_t)(r+8)*N + c + 1] = acc[mf][nf][3];
            }
        }
    }
}

// ---------------- dt = softplus(zx[:, DT_OFF+h] + dt_bias[h]) --------------------
__global__ void dt_kernel(const float* __restrict__ dt_bias)
{
    int idx = blockIdx.x * blockDim.x + threadIdx.x;
    if (idx >= BLTOT * NH) return;
    int bl = idx >> 5, hh = idx & 31;
    float v = g_zx[(size_t)bl * DPROJ + DT_OFF + hh] + dt_bias[hh];
    float sp = (v > 20.f) ? v : log1pf(expf(v));
    g_dt[idx] = sp;
}

// ---------------- depthwise causal conv (width 4) + silu + split -----------------
__global__ void conv_kernel(const float* __restrict__ conv_w,
                            const float* __restrict__ conv_b)
{
    int c = blockIdx.x * blockDim.x + threadIdx.x;
    if (c >= CONVD) return;
    int bl = blockIdx.y;
    int l = bl & (SEQ - 1);
    float acc = conv_b[c];
    #pragma unroll
    for (int kk = 0; kk < 4; kk++) {
        int lt = l + kk - 3;
        if (lt >= 0)
            acc += g_zx[(size_t)(bl + kk - 3) * DPROJ + XBC_OFF + c] * conv_w[c*4 + kk];
    }
    float a = acc / (1.f + __expf(-acc));
    if (c < DIN) {
        g_xs[(size_t)bl * DIN + c] = a;
    } else {
        int c2 = c - DIN;
        if (c2 < 64) {
            int k = c2 >> 1;
            if (c2 & 1) g_Bi[bl*NK + k] = a; else g_Br[bl*NK + k] = a;
        } else {
            int c3 = c2 - 64;
            int k = c3 >> 1;
            if (c3 & 1) g_Ci[bl*NK + k] = a; else g_Cr[bl*NK + k] = a;
        }
    }
}

// ---------------- t1 = tanh(x @ theta_w1)  tiled: 64 rows / block ----------------
__global__ __launch_bounds__(192) void lora1_kernel(const float* __restrict__ x,
                                                    const float* __restrict__ w1)
{
    __shared__ float xs[64][65];
    __shared__ float ws[64][LR];
    int tid = threadIdx.x;
    int row0 = blockIdx.x * 64;
    int n  = tid % LR;
    int rg = tid / LR;           // 0..3, each owns 16 rows
    float acc[16];
    #pragma unroll
    for (int i = 0; i < 16; i++) acc[i] = 0.f;

    for (int k0 = 0; k0 < DM; k0 += 64) {
        for (int idx = tid; idx < 64*64; idx += 192) {
            int r = idx >> 6, cc = idx & 63;
            xs[r][cc] = x[(size_t)(row0 + r)*DM + k0 + cc];
        }
        for (int idx = tid; idx < 64*LR; idx += 192) {
            int kk = idx / LR, nn = idx % LR;
            ws[kk][nn] = w1[(size_t)(k0 + kk)*LR + nn];
        }
        __syncthreads();
        #pragma unroll 4
        for (int kk = 0; kk < 64; kk++) {
            float w = ws[kk][n];
            #pragma unroll
            for (int i = 0; i < 16; i++)
                acc[i] += xs[rg*16 + i][kk] * w;
        }
        __syncthreads();
    }
    #pragma unroll
    for (int i = 0; i < 16; i++)
        g_t1[(size_t)(row0 + rg*16 + i)*LR + n] = tanhf(acc[i]);
}

// ---------------- lora2 -> theta -> lambda_eff -> log_z --------------------------
__global__ __launch_bounds__(256) void lora2_kernel(const float* __restrict__ w2,
                                                    const float* __restrict__ theta_base,
                                                    const float* __restrict__ lambda_base,
                                                    const float* __restrict__ eta)
{
    __shared__ float t1s[LR];
    int bl = blockIdx.x, tid = threadIdx.x;
    if (tid < LR) t1s[tid] = g_t1[bl*LR + tid];
    __syncthreads();
    for (int n = tid; n < NH*NK; n += 256) {
        float acc = 0.f;
        #pragma unroll
        for (int j = 0; j < LR; j++) acc += t1s[j] * w2[j*(NH*NK) + n];
        float th = theta_base[n] + acc;
        th = fminf(fmaxf(th, -THETA_CLIPF), THETA_CLIPF);
        float lam = lambda_base[n] + eta[n] * th * th;
        float dtv = g_dt[bl*NH + (n >> 5)];
        g_lzr[(size_t)bl*(NH*NK) + n] = -lam * dtv;
        g_lzi[(size_t)bl*(NH*NK) + n] =  th * dtv;
    }
}

// ---------------- per-chunk kernel: cumlog, G, y_intra, P/E, D -------------------
__global__ __launch_bounds__(256) void chunk_kernel(const float* __restrict__ Dvec)
{
    extern __shared__ float sm[];
    float* clr = sm;                 // 64 x 33
    float* cli = sm + 2112;
    float* Bre = sm + 2*2112;
    float* Bim = sm + 3*2112;
    float* Cre = sm + 4*2112;
    float* Cim = sm + 5*2112;
    float* xd  = sm + 6*2112;        // 64 x 65
    float* G   = sm + 6*2112 + 4160; // 64 x 65

    int tid = threadIdx.x;
    int bid = blockIdx.x;
    int h = bid & 31;
    int c = (bid >> 5) & 31;
    int b = bid >> 10;
    int blbase = b * SEQ + c * CH;

    for (int e = tid; e < CH*NK; e += 256) {
        int t = e >> 5, k = e & 31;
        int bl = blbase + t;
        clr[t*33+k] = g_lzr[(size_t)bl*(NH*NK) + h*NK + k];
        cli[t*33+k] = g_lzi[(size_t)bl*(NH*NK) + h*NK + k];
        Bre[t*33+k] = g_Br[bl*NK + k];
        Bim[t*33+k] = g_Bi[bl*NK + k];
        Cre[t*33+k] = g_Cr[bl*NK + k];
        Cim[t*33+k] = g_Ci[bl*NK + k];
    }
    for (int e = tid; e < CH*HD; e += 256) {
        int t = e >> 6, p = e & 63;
        int bl = blbase + t;
        xd[t*65+p] = g_xs[(size_t)bl*DIN + h*HD + p] * g_dt[bl*NH + h];
    }
    __syncthreads();

    if (tid < 32) {
        float sr = 0.f, si = 0.f;
        for (int t = 0; t < CH; t++) {
            sr += clr[t*33+tid]; si += cli[t*33+tid];
            clr[t*33+tid] = sr;  cli[t*33+tid] = si;
        }
    }
    __syncthreads();

    for (int e = tid; e < CH*NK; e += 256) {
        int t = e >> 5, k = e & 31;
        float er = __expf(clr[t*33+k]);
        float sn, cs; __sincosf(cli[t*33+k], &sn, &cs);
        float exr = er*cs, exi = er*sn;
        float cr = Cre[t*33+k], ci = Cim[t*33+k];
        size_t base = (size_t)bid*(CH*NK) + t*NK + k;
        g_Pr[base] = cr*exr - ci*exi;
        g_Pi[base] = cr*exi + ci*exr;
        if (t == CH-1) { g_Er[bid*NK + k] = exr; g_Ei[bid*NK + k] = exi; }
    }
    __syncthreads();

    for (int e = tid; e < CH*NK; e += 256) {
        int t = e >> 5, k = e & 31;
        float cr = Cre[t*33+k], ci = Cim[t*33+k];
        float br = Bre[t*33+k], bi = Bim[t*33+k];
        Cre[t*33+k] = cr*br - ci*bi;
        Cim[t*33+k] = cr*bi + ci*br;
    }
    __syncthreads();

    for (int e = tid; e < CH*CH; e += 256) {
        int t = e >> 6, s = e & 63;
        float acc = 0.f;
        if (s <= t) {
            #pragma unroll 4
            for (int k = 0; k < NK; k++) {
                float dr = clr[t*33+k] - clr[s*33+k];
                float di = cli[t*33+k] - cli[s*33+k];
                float er = __expf(dr);
                float sn, cs; __sincosf(di, &sn, &cs);
                acc += er * (Cre[t*33+k]*cs - Cim[t*33+k]*sn);
            }
        }
        G[t*65+s] = acc;
    }
    __syncthreads();

    float Dh = Dvec[h];
    for (int e = tid; e < CH*HD; e += 256) {
        int t = e >> 6, p = e & 63;
        float acc = 0.f;
        for (int s = 0; s <= t; s++) acc += G[t*65+s] * xd[s*65+p];
        size_t yi = (size_t)(blbase + t)*DIN + h*HD + p;
        g_y[yi] = acc + Dh * g_xs[yi];
    }

    for (int e = tid; e < CH*NK; e += 256) {
        int s = e >> 5, k = e & 31;
        float dr = clr[(CH-1)*33+k] - clr[s*33+k];
        float di = cli[(CH-1)*33+k] - cli[s*33+k];
        float er = __expf(dr);
        float sn, cs; __sincosf(di, &sn, &cs);
        Cre[s*33+k] = er*cs;
        Cim[s*33+k] = er*sn;
    }
    __syncthreads();

    for (int e = tid; e < HD*NK; e += 256) {
        int p = e >> 5, k = e & 31;
        float ar = 0.f, ai = 0.f;
        #pragma unroll 8
        for (int s = 0; s < CH; s++) {
            float xv = xd[s*65+p];
            ar += xv * Cre[s*33+k];
            ai += xv * Cim[s*33+k];
        }
        float br = Bre[(CH-1)*33+k], bi = Bim[(CH-1)*33+k];
        size_t di_ = (size_t)bid*(HD*NK) + p*NK + k;
        g_Dr[di_] = br*ar - bi*ai;
        g_Di[di_] = br*ai + bi*ar;
    }
}

// ---------------- sequential scan over chunks (per b,h,p,k) ----------------------
__global__ void scan_kernel()
{
    int idx = blockIdx.x * blockDim.x + threadIdx.x;
    int k = idx & 31;
    int p = (idx >> 5) & 63;
    int h = (idx >> 11) & 31;
    int b = idx >> 16;
    float sr = 0.f, si = 0.f;
    for (int c = 0; c < NCH; c++) {
        int bidl = (b*NCH + c)*NH + h;
        size_t di_ = (size_t)bidl*(HD*NK) + p*NK + k;
        g_Sr[di_] = sr; g_Si[di_] = si;
        float er = g_Er[bidl*NK + k], ei = g_Ei[bidl*NK + k];
        float dr = g_Dr[di_], dimg = g_Di[di_];
        float nr = er*sr - ei*si + dr;
        float ni = er*si + ei*sr + dimg;
        sr = nr; si = ni;
    }
}

// ---------------- y += Re( P[t,k] * S_entry[p,k] ) -------------------------------
__global__ __launch_bounds__(256) void yinter_kernel()
{
    __shared__ float Pr[2112], Pi[2112], Sr[2112], Si[2112];
    int tid = threadIdx.x, bid = blockIdx.x;
    int h = bid & 31, c = (bid >> 5) & 31, b = bid >> 10;
    size_t base = (size_t)bid * (CH*NK);
    for (int e = tid; e < CH*NK; e += 256) {
        int t = e >> 5, k = e & 31;
        Pr[t*33+k] = g_Pr[base + e];
        Pi[t*33+k] = g_Pi[base + e];
        Sr[t*33+k] = g_Sr[base + e];
        Si[t*33+k] = g_Si[base + e];
    }
    __syncthreads();
    int blbase = b*SEQ + c*CH;
    for (int e = tid; e < CH*HD; e += 256) {
        int t = e >> 6, p = e & 63;
        float acc = 0.f;
        #pragma unroll 8
        for (int k = 0; k < NK; k++)
            acc += Pr[t*33+k]*Sr[p*33+k] - Pi[t*33+k]*Si[p*33+k];
        size_t yi = (size_t)(blbase + t)*DIN + h*HD + p;
        g_y[yi] += acc;
    }
}

// ---------------- gating + RMSNorm ----------------------------------------------
__global__ __launch_bounds__(256) void gatenorm_kernel(const float* __restrict__ norm_w)
{
    __shared__ float red[8];
    int bl = blockIdx.x, tid = threadIdx.x;
    float local = 0.f;
    for (int j = tid; j < DIN; j += 256) {
        float z = g_zx[(size_t)bl*DPROJ + j];
        float y = g_y[(size_t)bl*DIN + j];
        float sig = 1.f / (1.f + __expf(-z));
        float g = y * z * sig;
        g_gv[(size_t)bl*DIN + j] = g;
        local += g * g;
    }
    #pragma unroll
    for (int o = 16; o; o >>= 1) local += __shfl_xor_sync(0xffffffffu, local, o);
    if ((tid & 31) == 0) red[tid >> 5] = local;
    __syncthreads();
    if (tid == 0) {
        float s = 0.f;
        for (int i = 0; i < 8; i++) s += red[i];
        red[0] = rsqrtf(s / (float)DIN + 1e-5f);
    }
    __syncthreads();
    float sc = red[0];
    for (int j = tid; j < DIN; j += 256)
        g_gv[(size_t)bl*DIN + j] *= sc * norm_w[j];
}

// ---------------- launch ---------------------------------------------------------
extern "C" void kernel_launch(void* const* d_in, const int* in_sizes, int n_in,
                              void* d_out, int out_size)
{
    (void)in_sizes; (void)n_in; (void)out_size;
    const float* x       = (const float*)d_in[0];
    const float* in_w    = (const float*)d_in[1];
    const float* conv_w  = (const float*)d_in[2];
    const float* conv_b  = (const float*)d_in[3];
    const float* dt_bias = (const float*)d_in[4];
    const float* lam_b   = (const float*)d_in[5];
    const float* th_b    = (const float*)d_in[6];
    const float* w1      = (const float*)d_in[7];
    const float* w2      = (const float*)d_in[8];
    const float* eta     = (const float*)d_in[9];
    const float* Dv      = (const float*)d_in[10];
    const float* nw      = (const float*)d_in[11];
    const float* out_w   = (const float*)d_in[12];
    float* out = (float*)d_out;

    float *zx = nullptr, *gg = nullptr;
    cudaGetSymbolAddress((void**)&zx, g_zx);
    cudaGetSymbolAddress((void**)&gg, g_gv);

    const int GEMM_SMEM = 4 * 128 * SMSTR * 2;   // 40960 B

    // 1) in_proj: [4096,1024] x [4256,1024]^T
    gemm_tc<<<dim3((DPROJ + 127)/128, BLTOT/128), 256, GEMM_SMEM>>>(x, in_w, zx, BLTOT, DPROJ, DM);
    // 2) dt
    dt_kernel<<<(BLTOT*NH + 255)/256, 256>>>(dt_bias);
    // 3) conv + silu + split
    conv_kernel<<<dim3((CONVD + 255)/256, BLTOT), 256>>>(conv_w, conv_b);
    // 4) lora stage 1 (tiled)
    lora1_kernel<<<BLTOT/64, 192>>>(x, w1);
    // 5) lora stage 2 + log_z
    lora2_kernel<<<BLTOT, 256>>>(w2, th_b, lam_b, eta);
    // 6) chunk-parallel heavy kernel
    cudaFuncSetAttribute(chunk_kernel, cudaFuncAttributeMaxDynamicSharedMemorySize, 84*1024);
    chunk_kernel<<<BATCHN*NCH*NH, 256, 83968>>>(Dv);
    // 7) inter-chunk state scan
    scan_kernel<<<(BATCHN*NH*HD*NK)/256, 256>>>();
    // 8) y += P * S_entry
    yinter_kernel<<<BATCHN*NCH*NH, 256>>>();
    // 9) gate + rmsnorm
    gatenorm_kernel<<<BLTOT, 256>>>(nw);
    // 10) out_proj: [4096,2048] x [1024,2048]^T
    gemm_tc<<<dim3(DM/128, BLTOT/128), 256, GEMM_SMEM>>>(gg, out_w, out, BLTOT, DM, DIN);
}

// round 4
// speedup vs baseline: 1.6574x; 1.0327x over previous
#include <cuda_runtime.h>
#include <cuda_bf16.h>
#include <math.h>

#define BATCHN 2
#define SEQ    2048
#define BLTOT  4096
#define DM     1024
#define DIN    2048
#define NH     32
#define HD     64
#define NK     32
#define CONVD  2176
#define DPROJ  4256
#define NCH    32
#define CH     64
#define LR     48
#define XBC_OFF 2048
#define DT_OFF  4224
#define THETA_CLIPF 1.5707963267948966f

// ---------------- scratch (static device globals; no allocation) ----------------
__device__ __align__(256) float g_zx [BLTOT*DPROJ];
__device__ __align__(256) float g_dt [BLTOT*NH];
__device__ __align__(256) float g_xs [BLTOT*DIN];
__device__ __align__(256) float g_Br [BLTOT*NK];
__device__ __align__(256) float g_Bi [BLTOT*NK];
__device__ __align__(256) float g_Cr [BLTOT*NK];
__device__ __align__(256) float g_Ci [BLTOT*NK];
__device__ __align__(256) float g_t1 [BLTOT*LR];
__device__ __align__(256) float g_lzr[BLTOT*NH*NK];
__device__ __align__(256) float g_lzi[BLTOT*NH*NK];
__device__ __align__(256) float g_Pr [BATCHN*NCH*NH*CH*NK];
__device__ __align__(256) float g_Pi [BATCHN*NCH*NH*CH*NK];
__device__ __align__(256) float g_Er [BATCHN*NCH*NH*NK];
__device__ __align__(256) float g_Ei [BATCHN*NCH*NH*NK];
__device__ __align__(256) float g_Dr [BATCHN*NCH*NH*HD*NK];
__device__ __align__(256) float g_Di [BATCHN*NCH*NH*HD*NK];
__device__ __align__(256) float g_Sr [BATCHN*NCH*NH*HD*NK];
__device__ __align__(256) float g_Si [BATCHN*NCH*NH*HD*NK];
__device__ __align__(256) float g_y  [BLTOT*DIN];
__device__ __align__(256) float g_gv [BLTOT*DIN];

// ================= tensor-core GEMM (bf16 2-term split, mma.sync) ===============
#define LDSM4(R0,R1,R2,R3,ADDR) \
    asm volatile("ldmatrix.sync.aligned.m8n8.x4.shared.b16 {%0,%1,%2,%3}, [%4];" \
                 : "=r"(R0),"=r"(R1),"=r"(R2),"=r"(R3) : "r"(ADDR))

__device__ __forceinline__ void mma_bf16(float* d, const unsigned* a,
                                         unsigned b0, unsigned b1)
{
    asm volatile("mma.sync.aligned.m16n8k16.row.col.f32.bf16.bf16.f32 "
                 "{%0,%1,%2,%3}, {%4,%5,%6,%7}, {%8,%9}, {%0,%1,%2,%3};"
                 : "+f"(d[0]), "+f"(d[1]), "+f"(d[2]), "+f"(d[3])
                 : "r"(a[0]), "r"(a[1]), "r"(a[2]), "r"(a[3]), "r"(b0), "r"(b1));
}

__device__ __forceinline__ unsigned smem_u32(const void* p)
{
    return (unsigned)__cvta_generic_to_shared(p);
}

__device__ __forceinline__ void split_store(float4 v,
                                            __nv_bfloat16* hi, __nv_bfloat16* lo)
{
    float xs[4] = {v.x, v.y, v.z, v.w};
    __nv_bfloat16 h[4], l[4];
    #pragma unroll
    for (int i = 0; i < 4; i++) {
        h[i] = __float2bfloat16(xs[i]);
        l[i] = __float2bfloat16(xs[i] - __bfloat162float(h[i]));
    }
    __nv_bfloat162 t;
    t.x = h[0]; t.y = h[1]; ((__nv_bfloat162*)hi)[0] = t;
    t.x = h[2]; t.y = h[3]; ((__nv_bfloat162*)hi)[1] = t;
    t.x = l[0]; t.y = l[1]; ((__nv_bfloat162*)lo)[0] = t;
    t.x = l[2]; t.y = l[3]; ((__nv_bfloat162*)lo)[1] = t;
}

#define SMSTR 40   // padded smem row stride (in bf16) -> conflict-free ldmatrix

__global__ __launch_bounds__(256) void gemm_tc(const float* __restrict__ A,
                                               const float* __restrict__ W,
                                               float* __restrict__ C,
                                               int M, int N, int Kd)
{
    extern __shared__ __align__(16) unsigned char smraw[];
    __nv_bfloat16* aHi = (__nv_bfloat16*)smraw;          // [128][SMSTR]
    __nv_bfloat16* aLo = aHi + 128*SMSTR;
    __nv_bfloat16* bHi = aLo + 128*SMSTR;
    __nv_bfloat16* bLo = bHi + 128*SMSTR;

    int tid = threadIdx.x, lane = tid & 31, wid = tid >> 5;
    int wm = wid & 3;          // m offset = 32*wm
    int wn = wid >> 2;         // n offset = 64*wn
    int row0 = blockIdx.y * 128, col0 = blockIdx.x * 128;

    float acc[2][8][4];
    #pragma unroll
    for (int a = 0; a < 2; a++)
        #pragma unroll
        for (int b = 0; b < 8; b++)
            #pragma unroll
            for (int c = 0; c < 4; c++) acc[a][b][c] = 0.f;

    float4 pa[4], pb[4];
    int NT = Kd >> 5;

    #pragma unroll
    for (int i = 0; i < 4; i++) {
        int f = tid + i*256, r = f >> 3, kq = f & 7;
        pa[i] = *(const float4*)(A + (size_t)(row0 + r)*Kd + kq*4);
        int wr = col0 + r;
        pb[i] = (wr < N) ? *(const float4*)(W + (size_t)wr*Kd + kq*4)
                         : make_float4(0.f,0.f,0.f,0.f);
    }
    #pragma unroll
    for (int i = 0; i < 4; i++) {
        int f = tid + i*256, r = f >> 3, kq = f & 7;
        split_store(pa[i], &aHi[r*SMSTR + kq*4], &aLo[r*SMSTR + kq*4]);
        split_store(pb[i], &bHi[r*SMSTR + kq*4], &bLo[r*SMSTR + kq*4]);
    }
    __syncthreads();

    for (int kt = 0; kt < NT; kt++) {
        if (kt + 1 < NT) {
            int k0 = (kt + 1) << 5;
            #pragma unroll
            for (int i = 0; i < 4; i++) {
                int f = tid + i*256, r = f >> 3, kq = f & 7;
                pa[i] = *(const float4*)(A + (size_t)(row0 + r)*Kd + k0 + kq*4);
                int wr = col0 + r;
                pb[i] = (wr < N) ? *(const float4*)(W + (size_t)wr*Kd + k0 + kq*4)
                                 : make_float4(0.f,0.f,0.f,0.f);
            }
        }

        #pragma unroll
        for (int kh = 0; kh < 32; kh += 16) {
            unsigned ah[2][4], al[2][4];
            #pragma unroll
            for (int mf = 0; mf < 2; mf++) {
                int r = wm*32 + mf*16 + (lane & 15);
                int cc = kh + ((lane >> 4) << 3);
                unsigned adr = smem_u32(&aHi[r*SMSTR + cc]);
                LDSM4(ah[mf][0], ah[mf][1], ah[mf][2], ah[mf][3], adr);
                adr = smem_u32(&aLo[r*SMSTR + cc]);
                LDSM4(al[mf][0], al[mf][1], al[mf][2], al[mf][3], adr);
            }
            #pragma unroll
            for (int np = 0; np < 4; np++) {
                int nr  = wn*64 + np*16 + (lane & 7) + ((lane >> 4) << 3);
                int kof = kh + (((lane >> 3) & 1) << 3);
                unsigned bh[4], bl[4];
                unsigned adr = smem_u32(&bHi[nr*SMSTR + kof]);
                LDSM4(bh[0], bh[1], bh[2], bh[3], adr);
                adr = smem_u32(&bLo[nr*SMSTR + kof]);
                LDSM4(bl[0], bl[1], bl[2], bl[3], adr);
                #pragma unroll
                for (int mf = 0; mf < 2; mf++) {
                    mma_bf16(acc[mf][np*2+0], ah[mf], bh[0], bh[1]);
                    mma_bf16(acc[mf][np*2+0], ah[mf], bl[0], bl[1]);
                    mma_bf16(acc[mf][np*2+0], al[mf], bh[0], bh[1]);
                    mma_bf16(acc[mf][np*2+1], ah[mf], bh[2], bh[3]);
                    mma_bf16(acc[mf][np*2+1], ah[mf], bl[2], bl[3]);
                    mma_bf16(acc[mf][np*2+1], al[mf], bh[2], bh[3]);
                }
            }
        }
        __syncthreads();
        if (kt + 1 < NT) {
            #pragma unroll
            for (int i = 0; i < 4; i++) {
                int f = tid + i*256, r = f >> 3, kq = f & 7;
                split_store(pa[i], &aHi[r*SMSTR + kq*4], &aLo[r*SMSTR + kq*4]);
                split_store(pb[i], &bHi[r*SMSTR + kq*4], &bLo[r*SMSTR + kq*4]);
            }
            __syncthreads();
        }
    }

    #pragma unroll
    for (int mf = 0; mf < 2; mf++) {
        int r = row0 + wm*32 + mf*16 + (lane >> 2);
        #pragma unroll
        for (int nf = 0; nf < 8; nf++) {
            int c = col0 + wn*64 + nf*8 + ((lane & 3) << 1);
            if (c + 1 < N) {
                *(float2*)&C[(size_t)r*N + c]     = make_float2(acc[mf][nf][0], acc[mf][nf][1]);
                *(float2*)&C[(size_t)(r+8)*N + c] = make_float2(acc[mf][nf][2], acc[mf][nf][3]);
            } else if (c < N) {
                C[(size_t)r*N + c]     = acc[mf][nf][0];
                C[(size_t)(r+8)*N + c] = acc[mf][nf][2];
            }
        }
    }
}

// ---------------- dt = softplus(zx[:, DT_OFF+h] + dt_bias[h]) --------------------
__global__ void dt_kernel(const float* __restrict__ dt_bias)
{
    int idx = blockIdx.x * blockDim.x + threadIdx.x;
    if (idx >= BLTOT * NH) return;
    int bl = idx >> 5, hh = idx & 31;
    float v = g_zx[(size_t)bl * DPROJ + DT_OFF + hh] + dt_bias[hh];
    float sp = (v > 20.f) ? v : log1pf(expf(v));
    g_dt[idx] = sp;
}

// ---------------- depthwise causal conv (width 4) + silu + split -----------------
__global__ void conv_kernel(const float* __restrict__ conv_w,
                            const float* __restrict__ conv_b)
{
    int c = blockIdx.x * blockDim.x + threadIdx.x;
    if (c >= CONVD) return;
    int bl = blockIdx.y;
    int l = bl & (SEQ - 1);
    float acc = conv_b[c];
    #pragma unroll
    for (int kk = 0; kk < 4; kk++) {
        int lt = l + kk - 3;
        if (lt >= 0)
            acc += g_zx[(size_t)(bl + kk - 3) * DPROJ + XBC_OFF + c] * conv_w[c*4 + kk];
    }
    float a = acc / (1.f + __expf(-acc));
    if (c < DIN) {
        g_xs[(size_t)bl * DIN + c] = a;
    } else {
        int c2 = c - DIN;
        if (c2 < 64) {
            int k = c2 >> 1;
            if (c2 & 1) g_Bi[bl*NK + k] = a; else g_Br[bl*NK + k] = a;
        } else {
            int c3 = c2 - 64;
            int k = c3 >> 1;
            if (c3 & 1) g_Ci[bl*NK + k] = a; else g_Cr[bl*NK + k] = a;
        }
    }
}

// ---------------- t1 = tanh(x @ theta_w1)  16 rows/block, 256 blocks -------------
__global__ __launch_bounds__(192) void lora1_kernel(const float* __restrict__ x,
                                                    const float* __restrict__ w1)
{
    __shared__ float xs[16][129];
    __shared__ float ws[128][49];
    int tid = threadIdx.x;
    int row0 = blockIdx.x * 16;
    int n  = tid % LR;           // 0..47
    int rg = tid / LR;           // 0..3 -> rows rg*4 .. rg*4+3
    float acc[4] = {0.f, 0.f, 0.f, 0.f};

    for (int k0 = 0; k0 < DM; k0 += 128) {
        for (int idx = tid; idx < 16*128; idx += 192) {
            int r = idx >> 7, cc = idx & 127;
            xs[r][cc] = x[(size_t)(row0 + r)*DM + k0 + cc];
        }
        for (int idx = tid; idx < 128*LR; idx += 192) {
            int kk = idx / LR, nn = idx % LR;
            ws[kk][nn] = w1[(size_t)(k0 + kk)*LR + nn];
        }
        __syncthreads();
        #pragma unroll 8
        for (int kk = 0; kk < 128; kk++) {
            float w = ws[kk][n];
            #pragma unroll
            for (int i = 0; i < 4; i++)
                acc[i] += xs[rg*4 + i][kk] * w;
        }
        __syncthreads();
    }
    #pragma unroll
    for (int i = 0; i < 4; i++)
        g_t1[(size_t)(row0 + rg*4 + i)*LR + n] = tanhf(acc[i]);
}

// ---------------- lora2 tiled: 64 rows x 256 cols per block ----------------------
__global__ __launch_bounds__(256) void lora2_kernel(const float* __restrict__ w2,
                                                    const float* __restrict__ theta_base,
                                                    const float* __restrict__ lambda_base,
                                                    const float* __restrict__ eta)
{
    __shared__ float t1s[64][LR];
    __shared__ float w2s[LR][256];
    int tid = threadIdx.x;
    int row0 = blockIdx.y * 64;
    int col0 = blockIdx.x * 256;
    int n = col0 + tid;

    for (int idx = tid; idx < 64*LR; idx += 256) {
        int r = idx / LR, j = idx % LR;
        t1s[r][j] = g_t1[(size_t)(row0 + r)*LR + j];
    }
    for (int idx = tid; idx < LR*256; idx += 256) {
        int j = idx >> 8, cc = idx & 255;
        w2s[j][cc] = w2[(size_t)j*(NH*NK) + col0 + cc];
    }
    __syncthreads();

    float tb = theta_base[n];
    float lb = lambda_base[n];
    float et = eta[n];
    int hh = n >> 5;

    for (int r = 0; r < 64; r++) {
        float acc = 0.f;
        #pragma unroll
        for (int j = 0; j < LR; j++) acc += t1s[r][j] * w2s[j][tid];
        float th = tb + acc;
        th = fminf(fmaxf(th, -THETA_CLIPF), THETA_CLIPF);
        float lam = lb + et * th * th;
        int bl = row0 + r;
        float dtv = g_dt[bl*NH + hh];
        g_lzr[(size_t)bl*(NH*NK) + n] = -lam * dtv;
        g_lzi[(size_t)bl*(NH*NK) + n] =  th * dtv;
    }
}

// ---------------- per-chunk kernel: cumlog, G, y_intra, P/E, D -------------------
__global__ __launch_bounds__(256) void chunk_kernel(const float* __restrict__ Dvec)
{
    extern __shared__ float sm[];
    float* clr = sm;                 // 64 x 33
    float* cli = sm + 2112;
    float* Bre = sm + 2*2112;
    float* Bim = sm + 3*2112;
    float* Cre = sm + 4*2112;
    float* Cim = sm + 5*2112;
    float* xd  = sm + 6*2112;        // 64 x 65
    float* G   = sm + 6*2112 + 4160; // 64 x 65

    int tid = threadIdx.x;
    int bid = blockIdx.x;
    int h = bid & 31;
    int c = (bid >> 5) & 31;
    int b = bid >> 10;
    int blbase = b * SEQ + c * CH;

    for (int e = tid; e < CH*NK; e += 256) {
        int t = e >> 5, k = e & 31;
        int bl = blbase + t;
        clr[t*33+k] = g_lzr[(size_t)bl*(NH*NK) + h*NK + k];
        cli[t*33+k] = g_lzi[(size_t)bl*(NH*NK) + h*NK + k];
        Bre[t*33+k] = g_Br[bl*NK + k];
        Bim[t*33+k] = g_Bi[bl*NK + k];
        Cre[t*33+k] = g_Cr[bl*NK + k];
        Cim[t*33+k] = g_Ci[bl*NK + k];
    }
    for (int e = tid; e < CH*HD; e += 256) {
        int t = e >> 6, p = e & 63;
        int bl = blbase + t;
        xd[t*65+p] = g_xs[(size_t)bl*DIN + h*HD + p] * g_dt[bl*NH + h];
    }
    __syncthreads();

    if (tid < 32) {
        float sr = 0.f, si = 0.f;
        for (int t = 0; t < CH; t++) {
            sr += clr[t*33+tid]; si += cli[t*33+tid];
            clr[t*33+tid] = sr;  cli[t*33+tid] = si;
        }
    }
    __syncthreads();

    for (int e = tid; e < CH*NK; e += 256) {
        int t = e >> 5, k = e & 31;
        float er = __expf(clr[t*33+k]);
        float sn, cs; __sincosf(cli[t*33+k], &sn, &cs);
        float exr = er*cs, exi = er*sn;
        float cr = Cre[t*33+k], ci = Cim[t*33+k];
        size_t base = (size_t)bid*(CH*NK) + t*NK + k;
        g_Pr[base] = cr*exr - ci*exi;
        g_Pi[base] = cr*exi + ci*exr;
        if (t == CH-1) { g_Er[bid*NK + k] = exr; g_Ei[bid*NK + k] = exi; }
    }
    __syncthreads();

    for (int e = tid; e < CH*NK; e += 256) {
        int t = e >> 5, k = e & 31;
        float cr = Cre[t*33+k], ci = Cim[t*33+k];
        float br = Bre[t*33+k], bi = Bim[t*33+k];
        Cre[t*33+k] = cr*br - ci*bi;
        Cim[t*33+k] = cr*bi + ci*br;
    }
    __syncthreads();

    for (int e = tid; e < CH*CH; e += 256) {
        int t = e >> 6, s = e & 63;
        float acc = 0.f;
        if (s <= t) {
            #pragma unroll 4
            for (int k = 0; k < NK; k++) {
                float dr = clr[t*33+k] - clr[s*33+k];
                if (dr > -27.f) {
                    float di = cli[t*33+k] - cli[s*33+k];
                    float er = __expf(dr);
                    float sn, cs; __sincosf(di, &sn, &cs);
                    acc += er * (Cre[t*33+k]*cs - Cim[t*33+k]*sn);
                }
            }
        }
        G[t*65+s] = acc;
    }
    __syncthreads();

    float Dh = Dvec[h];
    for (int e = tid; e < CH*HD; e += 256) {
        int t = e >> 6, p = e & 63;
        float acc = 0.f;
        for (int s = 0; s <= t; s++) acc += G[t*65+s] * xd[s*65+p];
        size_t yi = (size_t)(blbase + t)*DIN + h*HD + p;
        g_y[yi] = acc + Dh * g_xs[yi];
    }

    for (int e = tid; e < CH*NK; e += 256) {
        int s = e >> 5, k = e & 31;
        float dr = clr[(CH-1)*33+k] - clr[s*33+k];
        float di = cli[(CH-1)*33+k] - cli[s*33+k];
        float er = __expf(dr);
        float sn, cs; __sincosf(di, &sn, &cs);
        Cre[s*33+k] = er*cs;
        Cim[s*33+k] = er*sn;
    }
    __syncthreads();

    for (int e = tid; e < HD*NK; e += 256) {
        int p = e >> 5, k = e & 31;
        float ar = 0.f, ai = 0.f;
        #pragma unroll 8
        for (int s = 0; s < CH; s++) {
            float xv = xd[s*65+p];
            ar += xv * Cre[s*33+k];
            ai += xv * Cim[s*33+k];
        }
        float br = Bre[(CH-1)*33+k], bi = Bim[(CH-1)*33+k];
        size_t di_ = (size_t)bid*(HD*NK) + p*NK + k;
        g_Dr[di_] = br*ar - bi*ai;
        g_Di[di_] = br*ai + bi*ar;
    }
}

// ---------------- sequential scan over chunks (per b,h,p,k) ----------------------
__global__ void scan_kernel()
{
    int idx = blockIdx.x * blockDim.x + threadIdx.x;
    int k = idx & 31;
    int p = (idx >> 5) & 63;
    int h = (idx >> 11) & 31;
    int b = idx >> 16;
    float sr = 0.f, si = 0.f;
    for (int c = 0; c < NCH; c++) {
        int bidl = (b*NCH + c)*NH + h;
        size_t di_ = (size_t)bidl*(HD*NK) + p*NK + k;
        g_Sr[di_] = sr; g_Si[di_] = si;
        float er = g_Er[bidl*NK + k], ei = g_Ei[bidl*NK + k];
        float dr = g_Dr[di_], dimg = g_Di[di_];
        float nr = er*sr - ei*si + dr;
        float ni = er*si + ei*sr + dimg;
        sr = nr; si = ni;
    }
}

// ---------------- y += Re( P[t,k] * S_entry[p,k] ) -------------------------------
__global__ __launch_bounds__(256) void yinter_kernel()
{
    __shared__ float Pr[2112], Pi[2112], Sr[2112], Si[2112];
    int tid = threadIdx.x, bid = blockIdx.x;
    int h = bid & 31, c = (bid >> 5) & 31, b = bid >> 10;
    size_t base = (size_t)bid * (CH*NK);
    for (int e = tid; e < CH*NK; e += 256) {
        int t = e >> 5, k = e & 31;
        Pr[t*33+k] = g_Pr[base + e];
        Pi[t*33+k] = g_Pi[base + e];
        Sr[t*33+k] = g_Sr[base + e];
        Si[t*33+k] = g_Si[base + e];
    }
    __syncthreads();
    int blbase = b*SEQ + c*CH;
    for (int e = tid; e < CH*HD; e += 256) {
        int t = e >> 6, p = e & 63;
        float acc = 0.f;
        #pragma unroll 8
        for (int k = 0; k < NK; k++)
            acc += Pr[t*33+k]*Sr[p*33+k] - Pi[t*33+k]*Si[p*33+k];
        size_t yi = (size_t)(blbase + t)*DIN + h*HD + p;
        g_y[yi] += acc;
    }
}

// ---------------- gating + RMSNorm ----------------------------------------------
__global__ __launch_bounds__(256) void gatenorm_kernel(const float* __restrict__ norm_w)
{
    __shared__ float red[8];
    int bl = blockIdx.x, tid = threadIdx.x;
    float local = 0.f;
    for (int j = tid; j < DIN; j += 256) {
        float z = g_zx[(size_t)bl*DPROJ + j];
        float y = g_y[(size_t)bl*DIN + j];
        float sig = 1.f / (1.f + __expf(-z));
        float g = y * z * sig;
        g_gv[(size_t)bl*DIN + j] = g;
        local += g * g;
    }
    #pragma unroll
    for (int o = 16; o; o >>= 1) local += __shfl_xor_sync(0xffffffffu, local, o);
    if ((tid & 31) == 0) red[tid >> 5] = local;
    __syncthreads();
    if (tid == 0) {
        float s = 0.f;
        for (int i = 0; i < 8; i++) s += red[i];
        red[0] = rsqrtf(s / (float)DIN + 1e-5f);
    }
    __syncthreads();
    float sc = red[0];
    for (int j = tid; j < DIN; j += 256)
        g_gv[(size_t)bl*DIN + j] *= sc * norm_w[j];
}

// ---------------- launch ---------------------------------------------------------
extern "C" void kernel_launch(void* const* d_in, const int* in_sizes, int n_in,
                              void* d_out, int out_size)
{
    (void)in_sizes; (void)n_in; (void)out_size;
    const float* x       = (const float*)d_in[0];
    const float* in_w    = (const float*)d_in[1];
    const float* conv_w  = (const float*)d_in[2];
    const float* conv_b  = (const float*)d_in[3];
    const float* dt_bias = (const float*)d_in[4];
    const float* lam_b   = (const float*)d_in[5];
    const float* th_b    = (const float*)d_in[6];
    const float* w1      = (const float*)d_in[7];
    const float* w2      = (const float*)d_in[8];
    const float* eta     = (const float*)d_in[9];
    const float* Dv      = (const float*)d_in[10];
    const float* nw      = (const float*)d_in[11];
    const float* out_w   = (const float*)d_in[12];
    float* out = (float*)d_out;

    float *zx = nullptr, *gg = nullptr;
    cudaGetSymbolAddress((void**)&zx, g_zx);
    cudaGetSymbolAddress((void**)&gg, g_gv);

    const int GEMM_SMEM = 4 * 128 * SMSTR * 2;   // 40960 B

    // 1) in_proj: [4096,1024] x [4256,1024]^T
    gemm_tc<<<dim3((DPROJ + 127)/128, BLTOT/128), 256, GEMM_SMEM>>>(x, in_w, zx, BLTOT, DPROJ, DM);
    // 2) dt
    dt_kernel<<<(BLTOT*NH + 255)/256, 256>>>(dt_bias);
    // 3) conv + silu + split
    conv_kernel<<<dim3((CONVD + 255)/256, BLTOT), 256>>>(conv_w, conv_b);
    // 4) lora stage 1 (256 blocks)
    lora1_kernel<<<BLTOT/16, 192>>>(x, w1);
    // 5) lora stage 2 + log_z (tiled GEMM-style)
    lora2_kernel<<<dim3(4, BLTOT/64), 256>>>(w2, th_b, lam_b, eta);
    // 6) chunk-parallel heavy kernel
    cudaFuncSetAttribute(chunk_kernel, cudaFuncAttributeMaxDynamicSharedMemorySize, 84*1024);
    chunk_kernel<<<BATCHN*NCH*NH, 256, 83968>>>(Dv);
    // 7) inter-chunk state scan
    scan_kernel<<<(BATCHN*NH*HD*NK)/256, 256>>>();
    // 8) y += P * S_entry
    yinter_kernel<<<BATCHN*NCH*NH, 256>>>();
    // 9) gate + rmsnorm
    gatenorm_kernel<<<BLTOT, 256>>>(nw);
    // 10) out_proj: [4096,2048] x [1024,2048]^T
    gemm_tc<<<dim3(DM/128, BLTOT/128), 256, GEMM_SMEM>>>(gg, out_w, out, BLTOT, DM, DIN);
}